// round 4
// baseline (speedup 1.0000x reference)
#include <cuda_runtime.h>
#include <math.h>

// Problem dims
#define TT   4096
#define HH   1024
#define EE   8
#define II   1024
#define KTOP 2

// GEMM tiling
#define BM 64
#define BN 64
#define BK 16

#define CAP     (TT*KTOP + EE*BM)   // 8704 padded row capacity
#define TILES_M (CAP/BM)            // 136

// ---------------- device scratch (no allocs allowed) ----------------
__device__ int   g_counts[EE];
__device__ int   g_cursor[EE];
__device__ int   g_off[EE+1];
__device__ int   g_total;
__device__ int   g_perm[CAP];            // padded row -> token id (-1 = pad)
__device__ int   g_eid[TT*KTOP];         // token -> 2 expert ids
__device__ int   g_invrow[TT*KTOP];      // token slot -> padded row
__device__ float g_cw[TT*KTOP];          // token slot -> combine weight
__device__ float g_hact[(size_t)CAP*II]; // GEMM1 output (gelu(g)*u)
__device__ float g_ybuf[(size_t)CAP*HH]; // GEMM2 output

__device__ __forceinline__ float gelu_exact(float v) {
    return 0.5f * v * (1.0f + erff(v * 0.70710678118654752440f));
}

// ---------------- 1. init ----------------
__global__ void k_init() {
    int i = blockIdx.x * blockDim.x + threadIdx.x;
    if (i < CAP) g_perm[i] = -1;
    if (i < EE) { g_counts[i] = 0; g_cursor[i] = 0; }
}

// ---------------- 2. routing: softmax + top-2 + combine weights ----------------
__global__ void k_route(const float* __restrict__ logits,
                        const float* __restrict__ scale) {
    int t = blockIdx.x * blockDim.x + threadIdx.x;
    if (t >= TT) return;
    float l[EE];
    float mx = -1e30f;
    #pragma unroll
    for (int e = 0; e < EE; e++) {
        l[e] = logits[t * EE + e];
        mx = fmaxf(mx, l[e]);
    }
    float s = 0.f;
    #pragma unroll
    for (int e = 0; e < EE; e++) { l[e] = expf(l[e] - mx); s += l[e]; }

    // top-2 by prob (== top-2 by logit); strict > keeps lowest index on ties
    int i0 = 0;
    #pragma unroll
    for (int e = 1; e < EE; e++) if (l[e] > l[i0]) i0 = e;
    int i1 = (i0 == 0) ? 1 : 0;
    #pragma unroll
    for (int e = 0; e < EE; e++) if (e != i0 && l[e] > l[i1]) i1 = e;

    float p0 = l[i0] / s, p1 = l[i1] / s;
    float rn = p0 + p1;                 // > 0 always
    float w0 = (p0 / rn) * scale[i0];
    float w1 = (p1 / rn) * scale[i1];

    g_eid[t*KTOP+0] = i0;  g_eid[t*KTOP+1] = i1;
    g_cw [t*KTOP+0] = w0;  g_cw [t*KTOP+1] = w1;
    atomicAdd(&g_counts[i0], 1);
    atomicAdd(&g_counts[i1], 1);
}

// ---------------- 3. padded prefix offsets ----------------
__global__ void k_offsets() {
    int off = 0;
    g_off[0] = 0;
    for (int e = 0; e < EE; e++) {
        off += ((g_counts[e] + BM - 1) / BM) * BM;  // pad to BM so tiles are single-expert
        g_off[e+1] = off;
    }
    g_total = off;
}

// ---------------- 4. scatter tokens into expert segments ----------------
__global__ void k_scatter() {
    int t = blockIdx.x * blockDim.x + threadIdx.x;
    if (t >= TT) return;
    #pragma unroll
    for (int j = 0; j < KTOP; j++) {
        int e = g_eid[t*KTOP+j];
        int pos = atomicAdd(&g_cursor[e], 1);
        int r = g_off[e] + pos;
        g_perm[r] = t;
        g_invrow[t*KTOP+j] = r;
    }
}

// ---------------- 5. GEMM1: h = gelu(Xg @ w1^T) * (Xg @ w3^T) ----------------
__global__ __launch_bounds__(256)
void k_gemm1(const float* __restrict__ x, const float* __restrict__ w13) {
    __shared__ float As[BM][BK+4];   // m-major, padded for conflict-free frag reads
    __shared__ float Bg[BK][BN];     // k-major for float4 frag reads
    __shared__ float Bu[BK][BN];

    int row0 = blockIdx.x * BM;
    if (row0 >= g_total) return;

    int e = 0;
    #pragma unroll
    for (int q = 1; q < EE; q++) if (row0 >= g_off[q]) e = q;

    int n0  = blockIdx.y * BN;
    int tid = threadIdx.x;
    int lr  = tid >> 2;          // 0..63 (tile row for loads)
    int lc  = (tid & 3) << 2;    // 0,4,8,12 (k-chunk)
    int ty  = tid >> 4;          // 0..15 -> m microtile
    int tx  = tid & 15;          // 0..15 -> n microtile

    int tok = g_perm[row0 + lr];
    bool act = (tok >= 0);
    const float* xp  = x + (size_t)(act ? tok : 0) * HH + lc;
    const float* w1p = w13 + ((size_t)e * (2*II) + n0 + lr) * HH + lc;
    const float* w3p = w1p + (size_t)II * HH;

    float4 aR = act ? *(const float4*)xp : make_float4(0.f,0.f,0.f,0.f);
    float4 gR = *(const float4*)w1p;
    float4 uR = *(const float4*)w3p;

    float ag[4][4], au[4][4];
    #pragma unroll
    for (int i = 0; i < 4; i++)
        #pragma unroll
        for (int j = 0; j < 4; j++) { ag[i][j] = 0.f; au[i][j] = 0.f; }

    for (int k0 = 0; k0 < HH; k0 += BK) {
        *(float4*)&As[lr][lc] = aR;
        Bg[lc+0][lr] = gR.x; Bg[lc+1][lr] = gR.y; Bg[lc+2][lr] = gR.z; Bg[lc+3][lr] = gR.w;
        Bu[lc+0][lr] = uR.x; Bu[lc+1][lr] = uR.y; Bu[lc+2][lr] = uR.z; Bu[lc+3][lr] = uR.w;
        __syncthreads();

        if (k0 + BK < HH) {   // register prefetch of next tile overlaps compute
            int kn = k0 + BK;
            aR = act ? *(const float4*)(xp + kn) : make_float4(0.f,0.f,0.f,0.f);
            gR = *(const float4*)(w1p + kn);
            uR = *(const float4*)(w3p + kn);
        }

        #pragma unroll
        for (int kk = 0; kk < BK; kk++) {
            float av[4];
            #pragma unroll
            for (int mi = 0; mi < 4; mi++) av[mi] = As[ty*4+mi][kk];
            float4 bg4 = *(const float4*)&Bg[kk][tx*4];
            float4 bu4 = *(const float4*)&Bu[kk][tx*4];
            float bgv[4] = {bg4.x, bg4.y, bg4.z, bg4.w};
            float buv[4] = {bu4.x, bu4.y, bu4.z, bu4.w};
            #pragma unroll
            for (int mi = 0; mi < 4; mi++)
                #pragma unroll
                for (int ni = 0; ni < 4; ni++) {
                    ag[mi][ni] += av[mi] * bgv[ni];
                    au[mi][ni] += av[mi] * buv[ni];
                }
        }
        __syncthreads();
    }

    #pragma unroll
    for (int mi = 0; mi < 4; mi++) {
        size_t r = (size_t)(row0 + ty*4 + mi);
        float4 hv;
        hv.x = gelu_exact(ag[mi][0]) * au[mi][0];
        hv.y = gelu_exact(ag[mi][1]) * au[mi][1];
        hv.z = gelu_exact(ag[mi][2]) * au[mi][2];
        hv.w = gelu_exact(ag[mi][3]) * au[mi][3];
        *(float4*)&g_hact[r * II + n0 + tx*4] = hv;
    }
}

// ---------------- 6. GEMM2: y = H @ w2^T ----------------
__global__ __launch_bounds__(256)
void k_gemm2(const float* __restrict__ w2) {
    __shared__ float As[BM][BK+4];
    __shared__ float Bs[BK][BN];

    int row0 = blockIdx.x * BM;
    if (row0 >= g_total) return;

    int e = 0;
    #pragma unroll
    for (int q = 1; q < EE; q++) if (row0 >= g_off[q]) e = q;

    int n0  = blockIdx.y * BN;
    int tid = threadIdx.x;
    int lr  = tid >> 2;
    int lc  = (tid & 3) << 2;
    int ty  = tid >> 4;
    int tx  = tid & 15;

    const float* ap = &g_hact[(size_t)(row0 + lr) * II + lc];
    const float* bp = w2 + ((size_t)e * HH + n0 + lr) * II + lc;

    float4 aR = *(const float4*)ap;
    float4 bR = *(const float4*)bp;

    float acc[4][4];
    #pragma unroll
    for (int i = 0; i < 4; i++)
        #pragma unroll
        for (int j = 0; j < 4; j++) acc[i][j] = 0.f;

    for (int k0 = 0; k0 < II; k0 += BK) {
        *(float4*)&As[lr][lc] = aR;
        Bs[lc+0][lr] = bR.x; Bs[lc+1][lr] = bR.y; Bs[lc+2][lr] = bR.z; Bs[lc+3][lr] = bR.w;
        __syncthreads();

        if (k0 + BK < II) {
            int kn = k0 + BK;
            aR = *(const float4*)(ap + kn);
            bR = *(const float4*)(bp + kn);
        }

        #pragma unroll
        for (int kk = 0; kk < BK; kk++) {
            float av[4];
            #pragma unroll
            for (int mi = 0; mi < 4; mi++) av[mi] = As[ty*4+mi][kk];
            float4 b4 = *(const float4*)&Bs[kk][tx*4];
            float bv[4] = {b4.x, b4.y, b4.z, b4.w};
            #pragma unroll
            for (int mi = 0; mi < 4; mi++)
                #pragma unroll
                for (int ni = 0; ni < 4; ni++)
                    acc[mi][ni] += av[mi] * bv[ni];
        }
        __syncthreads();
    }

    #pragma unroll
    for (int mi = 0; mi < 4; mi++) {
        size_t r = (size_t)(row0 + ty*4 + mi);
        float4 yv = make_float4(acc[mi][0], acc[mi][1], acc[mi][2], acc[mi][3]);
        *(float4*)&g_ybuf[r * HH + n0 + tx*4] = yv;
    }
}

// ---------------- 7. deterministic combine (no atomics) ----------------
__global__ void k_combine(float* __restrict__ out) {
    int idx = blockIdx.x * blockDim.x + threadIdx.x;  // float4 index, < T*H/4
    int t = idx >> 8;               // H/4 = 256 float4 per token
    int c = (idx & 255) << 2;
    float w0 = g_cw[t*KTOP+0], w1 = g_cw[t*KTOP+1];
    size_t r0 = (size_t)g_invrow[t*KTOP+0];
    size_t r1 = (size_t)g_invrow[t*KTOP+1];
    float4 y0 = *(const float4*)&g_ybuf[r0 * HH + c];
    float4 y1 = *(const float4*)&g_ybuf[r1 * HH + c];
    float4 o;
    o.x = w0*y0.x + w1*y1.x;
    o.y = w0*y0.y + w1*y1.y;
    o.z = w0*y0.z + w1*y1.z;
    o.w = w0*y0.w + w1*y1.w;
    *(float4*)&out[(size_t)t * HH + c] = o;
}

// ---------------- launch ----------------
extern "C" void kernel_launch(void* const* d_in, const int* in_sizes, int n_in,
                              void* d_out, int out_size) {
    const float* x      = (const float*)d_in[0];
    const float* logits = (const float*)d_in[1];
    const float* scale  = (const float*)d_in[2];
    const float* w13    = (const float*)d_in[3];
    const float* w2     = (const float*)d_in[4];
    float* out = (float*)d_out;

    k_init   <<<(CAP + 255) / 256, 256>>>();
    k_route  <<<TT / 256, 256>>>(logits, scale);
    k_offsets<<<1, 1>>>();
    k_scatter<<<TT / 256, 256>>>();
    k_gemm1  <<<dim3(TILES_M, II / BN), 256>>>(x, w13);
    k_gemm2  <<<dim3(TILES_M, HH / BN), 256>>>(w2);
    k_combine<<<(TT * HH / 4) / 256, 256>>>(out);
}

// round 13
// speedup vs baseline: 1.8035x; 1.8035x over previous
#include <cuda_runtime.h>
#include <math.h>
#include <stdint.h>

// Problem dims
#define TT   4096
#define HH   1024
#define EE   8
#define II   1024
#define KTOP 2

// GEMM tiling (tf32 mma.sync path)
#define BM   128
#define BN   128
#define BKF  32                 // K floats per smem chunk (128B rows)
#define NCH  32                 // 1024 / 32 K-chunks

#define CAP     (TT*KTOP + EE*BM)   // 9216 padded row capacity
#define TILES_M (CAP/BM)            // 72

// ---------------- device scratch (no allocs allowed) ----------------
__device__ int   g_counts[EE];
__device__ int   g_cursor[EE];
__device__ int   g_off[EE+1];
__device__ int   g_total;
__device__ int   g_perm[CAP];
__device__ int   g_eid[TT*KTOP];
__device__ int   g_invrow[TT*KTOP];
__device__ float g_cw[TT*KTOP];
__device__ float g_big[(size_t)CAP*2*II];   // GEMM1 raw [CAP][2048] (g | u)
__device__ float g_hact[(size_t)CAP*II];    // gelu(g)*u
__device__ float g_ybuf[(size_t)CAP*HH];    // GEMM2 out

// ---------------- helpers ----------------
__device__ __forceinline__ uint32_t smem_u32(const void* p) {
    uint32_t a;
    asm("{ .reg .u64 t; cvta.to.shared.u64 t, %1; cvt.u32.u64 %0, t; }" : "=r"(a) : "l"(p));
    return a;
}
__device__ __forceinline__ float gelu_exact(float v) {
    return 0.5f * v * (1.0f + erff(v * 0.70710678118654752440f));
}
// tf32 hi/lo split: hi keeps the 10 explicit tf32 mantissa bits (exact in tf32),
// lo is the exact fp32 remainder (|lo| <= 2^-10 |v|).
__device__ __forceinline__ void tf32_split(uint32_t v, uint32_t& hi, uint32_t& lo) {
    hi = v & 0xFFFFE000u;
    lo = __float_as_uint(__uint_as_float(v) - __uint_as_float(hi));
}

// ---------------- 1. init ----------------
__global__ void k_init() {
    int i = blockIdx.x * blockDim.x + threadIdx.x;
    if (i < CAP) g_perm[i] = -1;
    if (i < EE) { g_counts[i] = 0; g_cursor[i] = 0; }
}

// ---------------- 2. routing ----------------
__global__ void k_route(const float* __restrict__ logits,
                        const float* __restrict__ scale) {
    int t = blockIdx.x * blockDim.x + threadIdx.x;
    if (t >= TT) return;
    float l[EE];
    float mx = -1e30f;
    #pragma unroll
    for (int e = 0; e < EE; e++) { l[e] = logits[t*EE+e]; mx = fmaxf(mx, l[e]); }
    float s = 0.f;
    #pragma unroll
    for (int e = 0; e < EE; e++) { l[e] = expf(l[e]-mx); s += l[e]; }
    int i0 = 0;
    #pragma unroll
    for (int e = 1; e < EE; e++) if (l[e] > l[i0]) i0 = e;
    int i1 = (i0 == 0) ? 1 : 0;
    #pragma unroll
    for (int e = 0; e < EE; e++) if (e != i0 && l[e] > l[i1]) i1 = e;
    float p0 = l[i0]/s, p1 = l[i1]/s;
    float rn = p0 + p1;
    float w0 = (p0/rn) * scale[i0];
    float w1 = (p1/rn) * scale[i1];
    g_eid[t*KTOP+0] = i0; g_eid[t*KTOP+1] = i1;
    g_cw [t*KTOP+0] = w0; g_cw [t*KTOP+1] = w1;
    atomicAdd(&g_counts[i0], 1);
    atomicAdd(&g_counts[i1], 1);
}

// ---------------- 3. padded offsets (pad to BM=128) ----------------
__global__ void k_offsets() {
    int off = 0;
    g_off[0] = 0;
    for (int e = 0; e < EE; e++) {
        off += ((g_counts[e] + BM - 1) / BM) * BM;
        g_off[e+1] = off;
    }
    g_total = off;
}

// ---------------- 4. scatter ----------------
__global__ void k_scatter() {
    int t = blockIdx.x * blockDim.x + threadIdx.x;
    if (t >= TT) return;
    #pragma unroll
    for (int j = 0; j < KTOP; j++) {
        int e = g_eid[t*KTOP+j];
        int pos = atomicAdd(&g_cursor[e], 1);
        int r = g_off[e] + pos;
        g_perm[r] = t;
        g_invrow[t*KTOP+j] = r;
    }
}

// ---------------- 5/6. grouped GEMM via error-compensated tf32 mma.sync ----------------
// MODE 1: g_big[row][0:2048] = gather(x) @ w13[e]^T   (N=2048)
// MODE 2: g_ybuf[row][0:1024] = g_hact @ w2[e]^T      (N=1024)
// smem double buffer, 32KB each: A[128][32] @ +0, B[128][32] @ +16384.
#define GSMEM 65536

#define MMA_TF32(ACC, A0, A1, A2, A3, B0, B1) \
    asm volatile( \
        "mma.sync.aligned.m16n8k8.row.col.f32.tf32.tf32.f32 " \
        "{%0,%1,%2,%3}, {%4,%5,%6,%7}, {%8,%9}, {%0,%1,%2,%3};" \
        : "+f"((ACC)[0]), "+f"((ACC)[1]), "+f"((ACC)[2]), "+f"((ACC)[3]) \
        : "r"(A0), "r"(A1), "r"(A2), "r"(A3), "r"(B0), "r"(B1))

template<int MODE, int NN>
__global__ __launch_bounds__(256, 2)
void k_gemm_tc(const float* __restrict__ Ax, const float* __restrict__ W)
{
    extern __shared__ char smem[];
    int row0 = blockIdx.x * BM;
    if (row0 >= g_total) return;

    int e = 0;
    #pragma unroll
    for (int q = 1; q < EE; q++) if (row0 >= g_off[q]) e = q;
    int n0 = blockIdx.y * BN;

    uint32_t sb = smem_u32(smem);
    int tid = threadIdx.x;
    int lane = tid & 31, wid = tid >> 5;
    int wm = wid & 1;      // 2 warp-rows x 64
    int wn = wid >> 1;     // 4 warp-cols x 32

    const float* wbase = W + (size_t)e * NN * HH;

    // per-thread cp.async slots: 4 A float4 + 4 B float4 per K-chunk
    const float* pA[4]; int szA[4]; const float* pB[4]; uint32_t sOf[4];
    #pragma unroll
    for (int p = 0; p < 4; p++) {
        int pos = p*256 + tid;
        int r = pos >> 3, c = pos & 7;
        sOf[p] = (uint32_t)(r*128 + ((c ^ (r & 7)) << 4));   // 16B-chunk swizzle
        if (MODE == 1) {
            int tok = g_perm[row0 + r];
            pA[p] = Ax + (size_t)(tok < 0 ? 0 : tok) * HH + c*4;
            szA[p] = (tok < 0) ? 0 : 16;                     // zero-fill pad rows
        } else {
            pA[p] = &g_hact[(size_t)(row0 + r) * II + c*4];
            szA[p] = 16;
        }
        pB[p] = wbase + (size_t)(n0 + r) * HH + c*4;
    }

    // ldmatrix lane addressing (A: [m][k], B: [n][k]; same 128B-row swizzle)
    int xorv = lane & 7;
    uint32_t aRow = (uint32_t)((wm*64 + (lane & 7) + ((lane >> 3) & 1)*8) * 128);
    int aCsel = (lane >> 4) & 1;
    uint32_t bRow = (uint32_t)((wn*32 + (lane & 7) + ((lane >> 4) & 1)*8) * 128);
    int bCsel = (lane >> 3) & 1;
    uint32_t aSw[4], bSw[4];
    #pragma unroll
    for (int ks = 0; ks < 4; ks++) {
        aSw[ks] = aRow + (uint32_t)((((2*ks + aCsel) ^ xorv)) << 4);
        bSw[ks] = bRow + (uint32_t)((((2*ks + bCsel) ^ xorv)) << 4);
    }

    float acc[4][4][4];
    #pragma unroll
    for (int i = 0; i < 4; i++)
        #pragma unroll
        for (int j = 0; j < 4; j++)
            #pragma unroll
            for (int q = 0; q < 4; q++) acc[i][j][q] = 0.f;

    // prologue: K-chunk 0
    {
        uint32_t ba = sb, bb = sb + 16384u;
        #pragma unroll
        for (int p = 0; p < 4; p++) {
            asm volatile("cp.async.cg.shared.global [%0], [%1], 16, %2;"
                :: "r"(ba + sOf[p]), "l"(pA[p]), "r"(szA[p]));
            asm volatile("cp.async.cg.shared.global [%0], [%1], 16;"
                :: "r"(bb + sOf[p]), "l"(pB[p]));
        }
        asm volatile("cp.async.commit_group;" ::: "memory");
    }

    for (int cdx = 0; cdx < NCH; cdx++) {
        if (cdx + 1 < NCH) {
            uint32_t ba = sb + (uint32_t)((cdx + 1) & 1) * 32768u;
            uint32_t bb = ba + 16384u;
            int k0 = (cdx + 1) * BKF;
            #pragma unroll
            for (int p = 0; p < 4; p++) {
                asm volatile("cp.async.cg.shared.global [%0], [%1], 16, %2;"
                    :: "r"(ba + sOf[p]), "l"(pA[p] + k0), "r"(szA[p]));
                asm volatile("cp.async.cg.shared.global [%0], [%1], 16;"
                    :: "r"(bb + sOf[p]), "l"(pB[p] + k0));
            }
            asm volatile("cp.async.commit_group;" ::: "memory");
            asm volatile("cp.async.wait_group 1;" ::: "memory");
        } else {
            asm volatile("cp.async.wait_group 0;" ::: "memory");
        }
        __syncthreads();

        uint32_t ba = sb + (uint32_t)(cdx & 1) * 32768u;
        uint32_t bb = ba + 16384u;
        #pragma unroll
        for (int ks = 0; ks < 4; ks++) {
            // B fragments + hi/lo split (kept live across all mt)
            uint32_t b[4][2], blo[4][2];
            #pragma unroll
            for (int p = 0; p < 2; p++) {
                uint32_t bd = bb + bSw[ks] + (uint32_t)(p * 2048);
                asm volatile("ldmatrix.sync.aligned.m8n8.x4.shared.b16 {%0,%1,%2,%3}, [%4];"
                    : "=r"(b[2*p][0]), "=r"(b[2*p][1]), "=r"(b[2*p+1][0]), "=r"(b[2*p+1][1])
                    : "r"(bd));
            }
            #pragma unroll
            for (int nt = 0; nt < 4; nt++)
                #pragma unroll
                for (int q = 0; q < 2; q++)
                    tf32_split(b[nt][q], b[nt][q], blo[nt][q]);

            #pragma unroll
            for (int mt = 0; mt < 4; mt++) {
                uint32_t a[4], alo[4];
                uint32_t ad = ba + aSw[ks] + (uint32_t)(mt * 2048);
                asm volatile("ldmatrix.sync.aligned.m8n8.x4.shared.b16 {%0,%1,%2,%3}, [%4];"
                    : "=r"(a[0]), "=r"(a[1]), "=r"(a[2]), "=r"(a[3])
                    : "r"(ad));
                #pragma unroll
                for (int q = 0; q < 4; q++)
                    tf32_split(a[q], a[q], alo[q]);

                #pragma unroll
                for (int nt = 0; nt < 4; nt++) {
                    // 3xTF32: hi*hi + lo*hi + hi*lo (lo*lo term ~2^-20, dropped)
                    MMA_TF32(acc[mt][nt], a[0], a[1], a[2], a[3], b[nt][0], b[nt][1]);
                    MMA_TF32(acc[mt][nt], alo[0], alo[1], alo[2], alo[3], b[nt][0], b[nt][1]);
                    MMA_TF32(acc[mt][nt], a[0], a[1], a[2], a[3], blo[nt][0], blo[nt][1]);
                }
            }
        }
        __syncthreads();
    }

    // epilogue
    float* C = (MODE == 1) ? g_big : g_ybuf;
    int rB = row0 + wm*64 + (lane >> 2);
    int cB = n0 + wn*32 + (lane & 3)*2;
    #pragma unroll
    for (int mt = 0; mt < 4; mt++) {
        #pragma unroll
        for (int nt = 0; nt < 4; nt++) {
            int rw = rB + mt*16;
            int cw = cB + nt*8;
            *(float2*)&C[(size_t)rw * NN + cw]     = make_float2(acc[mt][nt][0], acc[mt][nt][1]);
            *(float2*)&C[(size_t)(rw+8) * NN + cw] = make_float2(acc[mt][nt][2], acc[mt][nt][3]);
        }
    }
}

// ---------------- 5b. gelu(g)*u from raw GEMM1 output ----------------
__global__ void k_gelumul() {
    int idx = blockIdx.x * blockDim.x + threadIdx.x;  // float4 index
    int r = idx >> 8;                                 // 256 float4 per row
    if (r >= g_total) return;
    int c = (idx & 255) << 2;
    float4 g4 = *(const float4*)&g_big[(size_t)r * (2*II) + c];
    float4 u4 = *(const float4*)&g_big[(size_t)r * (2*II) + II + c];
    float4 h;
    h.x = gelu_exact(g4.x) * u4.x;
    h.y = gelu_exact(g4.y) * u4.y;
    h.z = gelu_exact(g4.z) * u4.z;
    h.w = gelu_exact(g4.w) * u4.w;
    *(float4*)&g_hact[(size_t)r * II + c] = h;
}

// ---------------- 7. deterministic combine ----------------
__global__ void k_combine(float* __restrict__ out) {
    int idx = blockIdx.x * blockDim.x + threadIdx.x;
    int t = idx >> 8;
    int c = (idx & 255) << 2;
    float w0 = g_cw[t*KTOP+0], w1 = g_cw[t*KTOP+1];
    size_t r0 = (size_t)g_invrow[t*KTOP+0];
    size_t r1 = (size_t)g_invrow[t*KTOP+1];
    float4 y0 = *(const float4*)&g_ybuf[r0 * HH + c];
    float4 y1 = *(const float4*)&g_ybuf[r1 * HH + c];
    float4 o;
    o.x = w0*y0.x + w1*y1.x;
    o.y = w0*y0.y + w1*y1.y;
    o.z = w0*y0.z + w1*y1.z;
    o.w = w0*y0.w + w1*y1.w;
    *(float4*)&out[(size_t)t * HH + c] = o;
}

// ---------------- launch ----------------
extern "C" void kernel_launch(void* const* d_in, const int* in_sizes, int n_in,
                              void* d_out, int out_size) {
    const float* x      = (const float*)d_in[0];
    const float* logits = (const float*)d_in[1];
    const float* scale  = (const float*)d_in[2];
    const float* w13    = (const float*)d_in[3];
    const float* w2     = (const float*)d_in[4];
    float* out = (float*)d_out;

    cudaFuncSetAttribute(k_gemm_tc<1, 2*II>, cudaFuncAttributeMaxDynamicSharedMemorySize, GSMEM);
    cudaFuncSetAttribute(k_gemm_tc<2, HH>,   cudaFuncAttributeMaxDynamicSharedMemorySize, GSMEM);

    k_init   <<<(CAP + 255) / 256, 256>>>();
    k_route  <<<TT / 256, 256>>>(logits, scale);
    k_offsets<<<1, 1>>>();
    k_scatter<<<TT / 256, 256>>>();
    k_gemm_tc<1, 2*II><<<dim3(TILES_M, (2*II)/BN), 256, GSMEM>>>(x, w13);
    k_gelumul<<<CAP, 256>>>();
    k_gemm_tc<2, HH><<<dim3(TILES_M, HH/BN), 256, GSMEM>>>(x /*unused in MODE 2*/, w2);
    k_combine<<<(TT * HH / 4) / 256, 256>>>(out);
}

// round 16
// speedup vs baseline: 2.4998x; 1.3861x over previous
#include <cuda_runtime.h>
#include <cuda_bf16.h>
#include <math.h>
#include <stdint.h>

// Problem dims
#define TT   4096
#define HH   1024
#define EE   8
#define II   1024
#define KTOP 2

// GEMM tiling
#define BM   128
#define BN   128
#define BKF  32                 // K floats per chunk (bf16 tile rows = 64B)
#define NCH  32                 // 1024/32 K-chunks

#define CAP     (TT*KTOP + EE*BM)   // 9216
#define TILES_M (CAP/BM)            // 72

#define XN   (TT*HH)
#define W13N (EE*2*II*HH)
#define W2N  (EE*HH*II)

// ---------------- device scratch (no allocs allowed) ----------------
__device__ int   g_counts[EE];
__device__ int   g_cursor[EE];
__device__ int   g_off[EE+1];
__device__ int   g_total;
__device__ int   g_perm[CAP];
__device__ int   g_eid[TT*KTOP];
__device__ int   g_invrow[TT*KTOP];
__device__ float g_cw[TT*KTOP];
__device__ float g_big[(size_t)CAP*2*II];    // GEMM1 raw fp32 (g | u)
__device__ float g_ybuf[(size_t)CAP*HH];     // GEMM2 out fp32

// bf16 split operand buffers
__device__ __nv_bfloat16 g_xhi[XN],   g_xlo[XN];
__device__ __nv_bfloat16 g_w13hi[W13N], g_w13lo[W13N];
__device__ __nv_bfloat16 g_w2hi[W2N], g_w2lo[W2N];
__device__ __nv_bfloat16 g_hhi[(size_t)CAP*II], g_hlo[(size_t)CAP*II];

// ---------------- helpers ----------------
__device__ __forceinline__ uint32_t smem_u32(const void* p) {
    uint32_t a;
    asm("{ .reg .u64 t; cvta.to.shared.u64 t, %1; cvt.u32.u64 %0, t; }" : "=r"(a) : "l"(p));
    return a;
}
__device__ __forceinline__ float gelu_exact(float v) {
    return 0.5f * v * (1.0f + erff(v * 0.70710678118654752440f));
}
__device__ __forceinline__ uint32_t bfpack(__nv_bfloat16 a, __nv_bfloat16 b) {
    __nv_bfloat162 t(a, b);
    return *reinterpret_cast<uint32_t*>(&t);
}
__device__ __forceinline__ void bfsplit(float v, __nv_bfloat16& h, __nv_bfloat16& l) {
    h = __float2bfloat16_rn(v);
    l = __float2bfloat16_rn(v - __bfloat162float(h));
}

// ---------------- 1. init ----------------
__global__ void k_init() {
    int i = blockIdx.x * blockDim.x + threadIdx.x;
    if (i < CAP) g_perm[i] = -1;
    if (i < EE) { g_counts[i] = 0; g_cursor[i] = 0; }
}

// ---------------- 2. routing ----------------
__global__ void k_route(const float* __restrict__ logits,
                        const float* __restrict__ scale) {
    int t = blockIdx.x * blockDim.x + threadIdx.x;
    if (t >= TT) return;
    float l[EE];
    float mx = -1e30f;
    #pragma unroll
    for (int e = 0; e < EE; e++) { l[e] = logits[t*EE+e]; mx = fmaxf(mx, l[e]); }
    float s = 0.f;
    #pragma unroll
    for (int e = 0; e < EE; e++) { l[e] = expf(l[e]-mx); s += l[e]; }
    int i0 = 0;
    #pragma unroll
    for (int e = 1; e < EE; e++) if (l[e] > l[i0]) i0 = e;
    int i1 = (i0 == 0) ? 1 : 0;
    #pragma unroll
    for (int e = 0; e < EE; e++) if (e != i0 && l[e] > l[i1]) i1 = e;
    float p0 = l[i0]/s, p1 = l[i1]/s;
    float rn = p0 + p1;
    float w0 = (p0/rn) * scale[i0];
    float w1 = (p1/rn) * scale[i1];
    g_eid[t*KTOP+0] = i0; g_eid[t*KTOP+1] = i1;
    g_cw [t*KTOP+0] = w0; g_cw [t*KTOP+1] = w1;
    atomicAdd(&g_counts[i0], 1);
    atomicAdd(&g_counts[i1], 1);
}

// ---------------- 3. padded offsets ----------------
__global__ void k_offsets() {
    int off = 0;
    g_off[0] = 0;
    for (int e = 0; e < EE; e++) {
        off += ((g_counts[e] + BM - 1) / BM) * BM;
        g_off[e+1] = off;
    }
    g_total = off;
}

// ---------------- 4. scatter ----------------
__global__ void k_scatter() {
    int t = blockIdx.x * blockDim.x + threadIdx.x;
    if (t >= TT) return;
    #pragma unroll
    for (int j = 0; j < KTOP; j++) {
        int e = g_eid[t*KTOP+j];
        int pos = atomicAdd(&g_cursor[e], 1);
        int r = g_off[e] + pos;
        g_perm[r] = t;
        g_invrow[t*KTOP+j] = r;
    }
}

// ---------------- 4b. fp32 -> bf16 hi/lo split (x, w13, w2) ----------------
template<int DST>
__global__ void k_conv(const float* __restrict__ src, int n4) {
    int i = blockIdx.x * blockDim.x + threadIdx.x;
    if (i >= n4) return;
    __nv_bfloat16* hi = (DST == 0) ? g_xhi : (DST == 1) ? g_w13hi : g_w2hi;
    __nv_bfloat16* lo = (DST == 0) ? g_xlo : (DST == 1) ? g_w13lo : g_w2lo;
    float4 v = ((const float4*)src)[i];
    __nv_bfloat16 h0,h1,h2,h3, l0,l1,l2,l3;
    bfsplit(v.x, h0, l0); bfsplit(v.y, h1, l1);
    bfsplit(v.z, h2, l2); bfsplit(v.w, h3, l3);
    *(uint2*)&hi[(size_t)i*4] = make_uint2(bfpack(h0,h1), bfpack(h2,h3));
    *(uint2*)&lo[(size_t)i*4] = make_uint2(bfpack(l0,l1), bfpack(l2,l3));
}

// ---------------- 5/6. grouped GEMM via bf16x3 mma.sync ----------------
// MODE 1: g_big[row][0:2048] = gather(x) @ w13[e]^T   (A = x hi/lo via perm)
// MODE 2: g_ybuf[row][0:1024] = hact @ w2[e]^T        (A = g_hhi/g_hlo)
// smem per buffer (32KB): Ahi@0, Alo@8K, Bhi@16K, Blo@24K; tiles 128 rows x 64B,
// swizzle: phys = r*64 + ((c ^ ((r>>1)&3))<<4), c = 16B chunk 0..3.
#define GSMEM 65536

#define MMA_BF16(ACC, A, B0, B1) \
    asm volatile( \
        "mma.sync.aligned.m16n8k16.row.col.f32.bf16.bf16.f32 " \
        "{%0,%1,%2,%3}, {%4,%5,%6,%7}, {%8,%9}, {%0,%1,%2,%3};" \
        : "+f"((ACC)[0]), "+f"((ACC)[1]), "+f"((ACC)[2]), "+f"((ACC)[3]) \
        : "r"((A)[0]), "r"((A)[1]), "r"((A)[2]), "r"((A)[3]), "r"(B0), "r"(B1))

#define LDSM4(R, ADDR) \
    asm volatile("ldmatrix.sync.aligned.m8n8.x4.shared.b16 {%0,%1,%2,%3}, [%4];" \
        : "=r"((R)[0]), "=r"((R)[1]), "=r"((R)[2]), "=r"((R)[3]) : "r"(ADDR))

template<int MODE, int NN>
__global__ __launch_bounds__(256, 2)
void k_gemm_bf()
{
    extern __shared__ char smem[];
    int row0 = blockIdx.x * BM;
    if (row0 >= g_total) return;

    int e = 0;
    #pragma unroll
    for (int q = 1; q < EE; q++) if (row0 >= g_off[q]) e = q;
    int n0 = blockIdx.y * BN;

    uint32_t sb = smem_u32(smem);
    int tid = threadIdx.x;
    int lane = tid & 31, wid = tid >> 5;
    int wm = wid & 1;      // 2 warp-rows x 64
    int wn = wid >> 1;     // 4 warp-cols x 32

    const __nv_bfloat16* Ah = (MODE == 1) ? g_xhi : g_hhi;
    const __nv_bfloat16* Bh = (MODE == 1) ? g_w13hi : g_w2hi;
    ptrdiff_t dA = ((MODE == 1) ? g_xlo : g_hlo) - Ah;
    ptrdiff_t dB = ((MODE == 1) ? g_w13lo : g_w2lo) - Bh;

    // per-thread cp.async slots: 2 x 16B per tile per chunk
    const __nv_bfloat16 *pAh[2], *pBh[2];
    int szA[2]; uint32_t sOf[2];
    #pragma unroll
    for (int s = 0; s < 2; s++) {
        int pos = s*256 + tid;
        int r = pos >> 2, c = pos & 3;
        sOf[s] = (uint32_t)(r*64 + ((c ^ ((r >> 1) & 3)) << 4));
        size_t abase;
        if (MODE == 1) {
            int tok = g_perm[row0 + r];
            abase = (size_t)(tok < 0 ? 0 : tok) * 1024;
            szA[s] = (tok < 0) ? 0 : 16;
        } else {
            abase = (size_t)(row0 + r) * 1024;
            szA[s] = 16;
        }
        pAh[s] = Ah + abase + c*8;
        pBh[s] = Bh + (size_t)e * NN * 1024 + (size_t)(n0 + r) * 1024 + c*8;
    }

    // ldmatrix lane addressing
    uint32_t r0a = (uint32_t)(wm*64 + (lane & 7) + ((lane >> 3) & 1)*8);
    uint32_t r0b = (uint32_t)(wn*32 + (lane & 7) + ((lane >> 3) & 1)*8);
    int csel = (lane >> 4) & 1;
    uint32_t aSw[2], bSw[2];
    #pragma unroll
    for (int kk = 0; kk < 2; kk++) {
        uint32_t ca = (uint32_t)(2*kk + csel);
        aSw[kk] = r0a*64 + ((ca ^ ((r0a >> 1) & 3)) << 4);
        bSw[kk] = r0b*64 + ((ca ^ ((r0b >> 1) & 3)) << 4);
    }

    float acc[4][4][4];
    #pragma unroll
    for (int i = 0; i < 4; i++)
        #pragma unroll
        for (int j = 0; j < 4; j++)
            #pragma unroll
            for (int q = 0; q < 4; q++) acc[i][j][q] = 0.f;

    // prologue: chunk 0
    {
        uint32_t t0 = sb;
        #pragma unroll
        for (int s = 0; s < 2; s++) {
            asm volatile("cp.async.cg.shared.global [%0], [%1], 16, %2;"
                :: "r"(t0 +          sOf[s]), "l"(pAh[s]),      "r"(szA[s]));
            asm volatile("cp.async.cg.shared.global [%0], [%1], 16, %2;"
                :: "r"(t0 + 8192u  + sOf[s]), "l"(pAh[s] + dA), "r"(szA[s]));
            asm volatile("cp.async.cg.shared.global [%0], [%1], 16;"
                :: "r"(t0 + 16384u + sOf[s]), "l"(pBh[s]));
            asm volatile("cp.async.cg.shared.global [%0], [%1], 16;"
                :: "r"(t0 + 24576u + sOf[s]), "l"(pBh[s] + dB));
        }
        asm volatile("cp.async.commit_group;" ::: "memory");
    }

    for (int cdx = 0; cdx < NCH; cdx++) {
        if (cdx + 1 < NCH) {
            uint32_t t0 = sb + (uint32_t)((cdx + 1) & 1) * 32768u;
            int k0 = (cdx + 1) * BKF;
            #pragma unroll
            for (int s = 0; s < 2; s++) {
                asm volatile("cp.async.cg.shared.global [%0], [%1], 16, %2;"
                    :: "r"(t0 +          sOf[s]), "l"(pAh[s] + k0),      "r"(szA[s]));
                asm volatile("cp.async.cg.shared.global [%0], [%1], 16, %2;"
                    :: "r"(t0 + 8192u  + sOf[s]), "l"(pAh[s] + dA + k0), "r"(szA[s]));
                asm volatile("cp.async.cg.shared.global [%0], [%1], 16;"
                    :: "r"(t0 + 16384u + sOf[s]), "l"(pBh[s] + k0));
                asm volatile("cp.async.cg.shared.global [%0], [%1], 16;"
                    :: "r"(t0 + 24576u + sOf[s]), "l"(pBh[s] + dB + k0));
            }
            asm volatile("cp.async.commit_group;" ::: "memory");
            asm volatile("cp.async.wait_group 1;" ::: "memory");
        } else {
            asm volatile("cp.async.wait_group 0;" ::: "memory");
        }
        __syncthreads();

        uint32_t base = sb + (uint32_t)(cdx & 1) * 32768u;
        #pragma unroll
        for (int kk = 0; kk < 2; kk++) {
            // B fragments hi/lo: x4 covers 16 n-rows (2 nt tiles)
            uint32_t bh[4][2], bl[4][2];
            #pragma unroll
            for (int ntp = 0; ntp < 2; ntp++) {
                uint32_t q[4];
                LDSM4(q, base + 16384u + bSw[kk] + (uint32_t)(ntp * 1024));
                bh[2*ntp+0][0] = q[0]; bh[2*ntp+0][1] = q[2];
                bh[2*ntp+1][0] = q[1]; bh[2*ntp+1][1] = q[3];
                LDSM4(q, base + 24576u + bSw[kk] + (uint32_t)(ntp * 1024));
                bl[2*ntp+0][0] = q[0]; bl[2*ntp+0][1] = q[2];
                bl[2*ntp+1][0] = q[1]; bl[2*ntp+1][1] = q[3];
            }
            #pragma unroll
            for (int mt = 0; mt < 4; mt++) {
                uint32_t ah[4], al[4];
                LDSM4(ah, base +         aSw[kk] + (uint32_t)(mt * 1024));
                LDSM4(al, base + 8192u + aSw[kk] + (uint32_t)(mt * 1024));
                #pragma unroll
                for (int nt = 0; nt < 4; nt++) {
                    // bf16x3: hi*hi + lo*hi + hi*lo (ll ~2^-18, dropped)
                    MMA_BF16(acc[mt][nt], ah, bh[nt][0], bh[nt][1]);
                    MMA_BF16(acc[mt][nt], al, bh[nt][0], bh[nt][1]);
                    MMA_BF16(acc[mt][nt], ah, bl[nt][0], bl[nt][1]);
                }
            }
        }
        __syncthreads();
    }

    // epilogue (m16n8 C layout, unchanged from validated tf32 path)
    float* C = (MODE == 1) ? g_big : g_ybuf;
    int rB = row0 + wm*64 + (lane >> 2);
    int cB = n0 + wn*32 + (lane & 3)*2;
    #pragma unroll
    for (int mt = 0; mt < 4; mt++) {
        #pragma unroll
        for (int nt = 0; nt < 4; nt++) {
            int rw = rB + mt*16;
            int cw = cB + nt*8;
            *(float2*)&C[(size_t)rw * NN + cw]     = make_float2(acc[mt][nt][0], acc[mt][nt][1]);
            *(float2*)&C[(size_t)(rw+8) * NN + cw] = make_float2(acc[mt][nt][2], acc[mt][nt][3]);
        }
    }
}

// ---------------- 5b. gelu(g)*u -> bf16 hi/lo ----------------
__global__ void k_gelumul() {
    int idx = blockIdx.x * blockDim.x + threadIdx.x;
    int r = idx >> 8;
    if (r >= g_total) return;
    int c = (idx & 255) << 2;
    float4 g4 = *(const float4*)&g_big[(size_t)r * (2*II) + c];
    float4 u4 = *(const float4*)&g_big[(size_t)r * (2*II) + II + c];
    float h0 = gelu_exact(g4.x) * u4.x;
    float h1 = gelu_exact(g4.y) * u4.y;
    float h2 = gelu_exact(g4.z) * u4.z;
    float h3 = gelu_exact(g4.w) * u4.w;
    __nv_bfloat16 a0,a1,a2,a3, b0,b1,b2,b3;
    bfsplit(h0, a0, b0); bfsplit(h1, a1, b1);
    bfsplit(h2, a2, b2); bfsplit(h3, a3, b3);
    *(uint2*)&g_hhi[(size_t)r * II + c] = make_uint2(bfpack(a0,a1), bfpack(a2,a3));
    *(uint2*)&g_hlo[(size_t)r * II + c] = make_uint2(bfpack(b0,b1), bfpack(b2,b3));
}

// ---------------- 7. deterministic combine ----------------
__global__ void k_combine(float* __restrict__ out) {
    int idx = blockIdx.x * blockDim.x + threadIdx.x;
    int t = idx >> 8;
    int c = (idx & 255) << 2;
    float w0 = g_cw[t*KTOP+0], w1 = g_cw[t*KTOP+1];
    size_t r0 = (size_t)g_invrow[t*KTOP+0];
    size_t r1 = (size_t)g_invrow[t*KTOP+1];
    float4 y0 = *(const float4*)&g_ybuf[r0 * HH + c];
    float4 y1 = *(const float4*)&g_ybuf[r1 * HH + c];
    float4 o;
    o.x = w0*y0.x + w1*y1.x;
    o.y = w0*y0.y + w1*y1.y;
    o.z = w0*y0.z + w1*y1.z;
    o.w = w0*y0.w + w1*y1.w;
    *(float4*)&out[(size_t)t * HH + c] = o;
}

// ---------------- launch ----------------
extern "C" void kernel_launch(void* const* d_in, const int* in_sizes, int n_in,
                              void* d_out, int out_size) {
    const float* x      = (const float*)d_in[0];
    const float* logits = (const float*)d_in[1];
    const float* scale  = (const float*)d_in[2];
    const float* w13    = (const float*)d_in[3];
    const float* w2     = (const float*)d_in[4];
    float* out = (float*)d_out;

    cudaFuncSetAttribute(k_gemm_bf<1, 2*II>, cudaFuncAttributeMaxDynamicSharedMemorySize, GSMEM);
    cudaFuncSetAttribute(k_gemm_bf<2, HH>,   cudaFuncAttributeMaxDynamicSharedMemorySize, GSMEM);

    k_init   <<<(CAP + 255) / 256, 256>>>();
    k_route  <<<TT / 256, 256>>>(logits, scale);
    k_offsets<<<1, 1>>>();
    k_scatter<<<TT / 256, 256>>>();
    k_conv<0><<<(XN/4)   / 256, 256>>>(x,   XN/4);
    k_conv<1><<<(W13N/4) / 256, 256>>>(w13, W13N/4);
    k_conv<2><<<(W2N/4)  / 256, 256>>>(w2,  W2N/4);
    k_gemm_bf<1, 2*II><<<dim3(TILES_M, (2*II)/BN), 256, GSMEM>>>();
    k_gelumul<<<CAP, 256>>>();
    k_gemm_bf<2, HH><<<dim3(TILES_M, HH/BN), 256, GSMEM>>>();
    k_combine<<<(TT * HH / 4) / 256, 256>>>(out);
}